// round 10
// baseline (speedup 1.0000x reference)
#include <cuda_runtime.h>
#include <math.h>

// VolatilityLoss: mean((std3(pred) - std3(targ))^2), window w=3.
// B=512, S=8192, L=8190 outputs/row.
// Software-pipelined sequential span: 512 blocks (1/row) x 256 threads,
// thread t walks elems [32t,32t+32) as 8 float4 iters with rotating prefetch;
// packed f32x2 rolling chain carries state across iters (no shuffles, no
// overlap refetch). Peek elems 32,33 loaded predicated UP FRONT.
// 6*var_i = e_i^2+e_{i+1}^2+(e_i+e_{i+1})^2; pair via one sqrt; deferred /6.

#define B_ROWS 512
#define S_LEN  8192
#define L_OUT  (S_LEN - 2)
#define NBLOCKS 512
#define NTHREADS 256

typedef unsigned long long u64;

__device__ float        g_partials[NBLOCKS];
__device__ unsigned int g_counter = 0;   // monotone across graph replays

__device__ __forceinline__ float sqrt_approx(float x) {
    float r;
    asm("sqrt.approx.f32 %0, %1;" : "=f"(r) : "f"(x));
    return r;
}

#define PACK2(dst, lo, hi) \
    asm("mov.b64 %0, {%1, %2};" : "=l"(dst) : "f"(lo), "f"(hi))
#define UNPACK2(lo, hi, src) \
    asm("mov.b64 {%0, %1}, %2;" : "=f"(lo), "=f"(hi) : "l"(src))
#define FMA2(dst, a, b, c) \
    asm("fma.rn.f32x2 %0, %1, %2, %3;" : "=l"(dst) : "l"(a), "l"(b), "l"(c))
#define ADD2(dst, a, b) \
    asm("add.rn.f32x2 %0, %1, %2;" : "=l"(dst) : "l"(a), "l"(b))
#define MUL2(dst, a, b) \
    asm("mul.rn.f32x2 %0, %1, %2;" : "=l"(dst) : "l"(a), "l"(b))

// Consume one element pair; completes window ending 2 elements back (if v).
#define STEP(pel, tel, v)                                   \
    do {                                                    \
        u64 Pn, E, Gc, F, GS, V;                            \
        PACK2(Pn, pel, tel);                                \
        FMA2(E, Pn, M1, Pc);      /* E = Pc - Pn */         \
        MUL2(Gc, E, E);                                     \
        ADD2(F, Ep, E);                                     \
        ADD2(GS, Gp, Gc);                                   \
        FMA2(V, F, F, GS);        /* {6vp, 6vt} >= 0 */     \
        if (v) {                                            \
            ADD2(accV, accV, V);                            \
            float _vp, _vt;                                 \
            UNPACK2(_vp, _vt, V);                           \
            accR += sqrt_approx(_vp * _vt);                 \
        }                                                   \
        Ep = E; Gp = Gc; Pc = Pn;                           \
    } while (0)

__global__ void __launch_bounds__(NTHREADS)
vol_loss_fused(const float* __restrict__ pred, const float* __restrict__ targ,
               float* __restrict__ out) {
    const int t = threadIdx.x;
    const float* pb = pred + ((size_t)blockIdx.x << 13) + (t << 5);
    const float* tb = targ + ((size_t)blockIdx.x << 13) + (t << 5);
    const float4* p4 = (const float4*)pb;
    const float4* t4 = (const float4*)tb;

    u64 M1, accV;
    PACK2(M1,   -1.0f, -1.0f);
    PACK2(accV,  0.0f,  0.0f);
    float accR = 0.0f;

    // Peek elements 32,33 (= next thread's 0,1), issued up front so they are
    // never on the tail critical path. Thread 255 is the row end: its last
    // two windows are invalid and the load would cross the row.
    const bool full = (t != NTHREADS - 1);
    float p32 = 0.f, p33 = 0.f, t32 = 0.f, t33 = 0.f;
    if (full) {
        float2 pe2 = ((const float2*)(pb + 32))[0];
        float2 te2 = ((const float2*)(tb + 32))[0];
        p32 = pe2.x; p33 = pe2.y; t32 = te2.x; t33 = te2.y;
    }

    // Pipelined walk: compute on (pC,tC) while (pN,tN) for the next iteration
    // is in flight. Chain state (Pc,Ep,Gp) rolls across iterations.
    u64 Pc, Ep, Gp;
    float4 pN = p4[0], tN = t4[0];

    #pragma unroll
    for (int it = 0; it < 8; ++it) {
        float4 pC = pN, tC = tN;
        if (it < 7) { pN = p4[it + 1]; tN = t4[it + 1]; }
        if (it == 0) {
            u64 P0;
            PACK2(P0, pC.x, tC.x);
            PACK2(Pc, pC.y, tC.y);
            FMA2(Ep, Pc, M1, P0);
            MUL2(Gp, Ep, Ep);
            STEP(pC.z, tC.z, true);
            STEP(pC.w, tC.w, true);
        } else {
            STEP(pC.x, tC.x, true);
            STEP(pC.y, tC.y, true);
            STEP(pC.z, tC.z, true);
            STEP(pC.w, tC.w, true);
        }
    }
    STEP(p32, t32, full);   // window 30
    STEP(p33, t33, full);   // window 31

    float vps, vts;
    UNPACK2(vps, vts, accV);
    float acc = (vps + vts) - 2.0f * accR;   // still scaled by 6

    // Deterministic intra-block reduction.
    const int lane = t & 31;
    #pragma unroll
    for (int o = 16; o > 0; o >>= 1)
        acc += __shfl_down_sync(0xffffffffu, acc, o);

    __shared__ float red[NTHREADS / 32];
    int warp = t >> 5;
    if (lane == 0) red[warp] = acc;
    __syncthreads();

    __shared__ bool is_last;
    if (t == 0) {
        float v = 0.0f;
        #pragma unroll
        for (int w = 0; w < NTHREADS / 32; ++w) v += red[w];
        g_partials[blockIdx.x] = v;
        __threadfence();
        unsigned int old = atomicAdd(&g_counter, 1u);
        is_last = ((old + 1u) % (unsigned)NBLOCKS) == 0u;
    }
    __syncthreads();

    if (!is_last) return;

    // Last block: deterministic final reduction; fold the deferred /6.
    __shared__ double sh[NTHREADS];
    double s = 0.0;
    for (int i = t; i < NBLOCKS; i += NTHREADS)
        s += (double)g_partials[i];
    sh[t] = s;
    __syncthreads();
    #pragma unroll
    for (int stride = NTHREADS / 2; stride > 0; stride >>= 1) {
        if (t < stride) sh[t] += sh[t + stride];
        __syncthreads();
    }
    if (t == 0)
        out[0] = (float)(sh[0] / (6.0 * (double)B_ROWS * (double)L_OUT));
}

extern "C" void kernel_launch(void* const* d_in, const int* in_sizes, int n_in,
                              void* d_out, int out_size) {
    const float* pred = (const float*)d_in[0];
    const float* targ = (const float*)d_in[1];
    vol_loss_fused<<<NBLOCKS, NTHREADS>>>(pred, targ, (float*)d_out);
}

// round 11
// speedup vs baseline: 1.2569x; 1.2569x over previous
#include <cuda_runtime.h>
#include <math.h>

// VolatilityLoss: mean((std3(pred) - std3(targ))^2), window w=3.
// B=512, S=8192, L=8190 outputs/row.
// Packed f32x2 rolling chain (pred lo lane, targ hi lane), 8 outputs/thread,
// 1024 blocks x 512 threads (exact cover), shuffle peek (lane31-only load),
// fused last-block finalize. 6*var_i = e_i^2+e_{i+1}^2+(e_i+e_{i+1})^2;
// (sqrt(vp)-sqrt(vt))^2 = (vp6+vt6-2*sqrt(vp6*vt6))/6 (deferred /6).

#define B_ROWS 512
#define S_LEN  8192
#define L_OUT  (S_LEN - 2)
#define NBLOCKS 1024
#define NTHREADS 512
// NBLOCKS*NTHREADS*8 == B_ROWS*S_LEN exactly

typedef unsigned long long u64;

__device__ float        g_partials[NBLOCKS];
__device__ unsigned int g_counter = 0;   // monotone across graph replays

__device__ __forceinline__ float sqrt_approx(float x) {
    float r;
    asm("sqrt.approx.f32 %0, %1;" : "=f"(r) : "f"(x));
    return r;
}

#define PACK2(dst, lo, hi) \
    asm("mov.b64 %0, {%1, %2};" : "=l"(dst) : "f"(lo), "f"(hi))
#define UNPACK2(lo, hi, src) \
    asm("mov.b64 {%0, %1}, %2;" : "=f"(lo), "=f"(hi) : "l"(src))
#define FMA2(dst, a, b, c) \
    asm("fma.rn.f32x2 %0, %1, %2, %3;" : "=l"(dst) : "l"(a), "l"(b), "l"(c))
#define ADD2(dst, a, b) \
    asm("add.rn.f32x2 %0, %1, %2;" : "=l"(dst) : "l"(a), "l"(b))
#define MUL2(dst, a, b) \
    asm("mul.rn.f32x2 %0, %1, %2;" : "=l"(dst) : "l"(a), "l"(b))

// Consume one element pair; completes the window ending 2 elems back (if v).
#define STEP(pel, tel, v)                                   \
    do {                                                    \
        u64 Pn, E, Gc, F, GS, V;                            \
        PACK2(Pn, pel, tel);                                \
        FMA2(E, Pn, M1, Pc);      /* E = Pc - Pn */         \
        MUL2(Gc, E, E);                                     \
        ADD2(F, Ep, E);                                     \
        ADD2(GS, Gp, Gc);                                   \
        FMA2(V, F, F, GS);        /* {6vp, 6vt} >= 0 */     \
        if (v) {                                            \
            ADD2(accV, accV, V);                            \
            float _vp, _vt;                                 \
            UNPACK2(_vp, _vt, V);                           \
            accR += sqrt_approx(_vp * _vt);                 \
        }                                                   \
        Ep = E; Gp = Gc; Pc = Pn;                           \
    } while (0)

__global__ void __launch_bounds__(NTHREADS)
vol_loss_fused(const float* __restrict__ pred, const float* __restrict__ targ,
               float* __restrict__ out) {
    const int t    = threadIdx.x;
    const int lane = t & 31;
    const int g    = blockIdx.x * NTHREADS + t;
    const int row   = g >> 10;           // 1024 8-spans per row
    const int start = (g & 1023) << 3;

    const float* pb = pred + ((size_t)row << 13) + start;
    const float* tb = targ + ((size_t)row << 13) + start;

    // 4 front-batched LDG.128 (fully coalesced: warp covers 1KB contiguous).
    float4 pA = ((const float4*)pb)[0];
    float4 pB = ((const float4*)pb)[1];
    float4 tA = ((const float4*)tb)[0];
    float4 tB = ((const float4*)tb)[1];

    // Elements 8,9 = lane+1's elements 0,1 (adjacent lanes are adjacent spans
    // within a row). Row boundary always lands on lane 31, which instead does
    // a predicated float2 load (2 lines per warp — negligible L1 traffic).
    bool full = (start + 8) < S_LEN;     // false only at row end (lane 31)
    float p8 = __shfl_down_sync(0xffffffffu, pA.x, 1);
    float p9 = __shfl_down_sync(0xffffffffu, pA.y, 1);
    float t8 = __shfl_down_sync(0xffffffffu, tA.x, 1);
    float t9 = __shfl_down_sync(0xffffffffu, tA.y, 1);
    if (lane == 31) {
        p8 = p9 = t8 = t9 = 0.0f;
        if (full) {
            float2 pe2 = ((const float2*)(pb + 8))[0];
            float2 te2 = ((const float2*)(tb + 8))[0];
            p8 = pe2.x; p9 = pe2.y; t8 = te2.x; t9 = te2.y;
        }
    }

    u64 M1, accV;
    PACK2(M1,   -1.0f, -1.0f);
    PACK2(accV,  0.0f,  0.0f);
    float accR = 0.0f;

    // Rolling packed difference chain over elements 0..9 (windows 0..7).
    u64 P0, Pc, Ep, Gp;
    PACK2(P0, pA.x, tA.x);
    PACK2(Pc, pA.y, tA.y);
    FMA2(Ep, Pc, M1, P0);
    MUL2(Gp, Ep, Ep);

    STEP(pA.z, tA.z, true);
    STEP(pA.w, tA.w, true);
    STEP(pB.x, tB.x, true);
    STEP(pB.y, tB.y, true);
    STEP(pB.z, tB.z, true);
    STEP(pB.w, tB.w, true);
    STEP(p8,   t8,   full);
    STEP(p9,   t9,   full);

    float vps, vts;
    UNPACK2(vps, vts, accV);
    float acc = (vps + vts) - 2.0f * accR;   // still scaled by 6

    // Deterministic intra-block reduction.
    #pragma unroll
    for (int o = 16; o > 0; o >>= 1)
        acc += __shfl_down_sync(0xffffffffu, acc, o);

    __shared__ float red[NTHREADS / 32];
    int warp = t >> 5;
    if (lane == 0) red[warp] = acc;
    __syncthreads();

    __shared__ bool is_last;
    if (t == 0) {
        float v = 0.0f;
        #pragma unroll
        for (int w = 0; w < NTHREADS / 32; ++w) v += red[w];
        g_partials[blockIdx.x] = v;
        __threadfence();
        unsigned int old = atomicAdd(&g_counter, 1u);
        is_last = ((old + 1u) % (unsigned)NBLOCKS) == 0u;
    }
    __syncthreads();

    if (!is_last) return;

    // Last block: deterministic final reduction; fold the deferred /6.
    __shared__ double sh[NTHREADS];
    double s = 0.0;
    for (int i = t; i < NBLOCKS; i += NTHREADS)
        s += (double)g_partials[i];
    sh[t] = s;
    __syncthreads();
    #pragma unroll
    for (int stride = NTHREADS / 2; stride > 0; stride >>= 1) {
        if (t < stride) sh[t] += sh[t + stride];
        __syncthreads();
    }
    if (t == 0)
        out[0] = (float)(sh[0] / (6.0 * (double)B_ROWS * (double)L_OUT));
}

extern "C" void kernel_launch(void* const* d_in, const int* in_sizes, int n_in,
                              void* d_out, int out_size) {
    const float* pred = (const float*)d_in[0];
    const float* targ = (const float*)d_in[1];
    vol_loss_fused<<<NBLOCKS, NTHREADS>>>(pred, targ, (float*)d_out);
}

// round 12
// speedup vs baseline: 1.4837x; 1.1805x over previous
#include <cuda_runtime.h>
#include <math.h>
#include <stdint.h>

// VolatilityLoss: mean((std3(pred) - std3(targ))^2), window w=3.
// B=512, S=8192, L=8190 outputs/row.
// TMA-path kernel: each CTA bulk-copies its 4096-elem half-row (+16 peek)
// of both arrays into SMEM via cp.async.bulk + mbarrier, then computes the
// packed-f32x2 rolling chain from SMEM (conflict-free float4 LDS).
// 6*var_i = e_i^2+e_{i+1}^2+(e_i+e_{i+1})^2; pair via one sqrt; deferred /6.

#define B_ROWS 512
#define S_LEN  8192
#define L_OUT  (S_LEN - 2)
#define NBLOCKS 1024          // 2 per row
#define NTHREADS 256
#define CHUNK 4096            // elements per CTA per array
#define EXTRA 16              // peek elements

typedef unsigned long long u64;

__device__ float        g_partials[NBLOCKS];
__device__ unsigned int g_counter = 0;   // monotone across graph replays

__device__ __forceinline__ float sqrt_approx(float x) {
    float r;
    asm("sqrt.approx.f32 %0, %1;" : "=f"(r) : "f"(x));
    return r;
}

__device__ __forceinline__ uint32_t smem_u32(const void* p) {
    uint32_t a;
    asm("{ .reg .u64 t; cvta.to.shared.u64 t, %1; cvt.u32.u64 %0, t; }"
        : "=r"(a) : "l"(p));
    return a;
}

__device__ __forceinline__ void mbar_wait(uint32_t mbar, uint32_t parity) {
    asm volatile(
        "{\n\t.reg .pred P;\n"
        "W%=:\n\t"
        "mbarrier.try_wait.parity.acquire.cta.shared::cta.b64 P, [%0], %1, 0x989680;\n\t"
        "@!P bra W%=;\n\t}"
        :: "r"(mbar), "r"(parity) : "memory");
}

#define PACK2(dst, lo, hi) \
    asm("mov.b64 %0, {%1, %2};" : "=l"(dst) : "f"(lo), "f"(hi))
#define UNPACK2(lo, hi, src) \
    asm("mov.b64 {%0, %1}, %2;" : "=f"(lo), "=f"(hi) : "l"(src))
#define FMA2(dst, a, b, c) \
    asm("fma.rn.f32x2 %0, %1, %2, %3;" : "=l"(dst) : "l"(a), "l"(b), "l"(c))
#define ADD2(dst, a, b) \
    asm("add.rn.f32x2 %0, %1, %2;" : "=l"(dst) : "l"(a), "l"(b))
#define MUL2(dst, a, b) \
    asm("mul.rn.f32x2 %0, %1, %2;" : "=l"(dst) : "l"(a), "l"(b))

// Consume one element pair; completes the window ending 2 elems back (if v).
#define STEP(pel, tel, v)                                   \
    do {                                                    \
        u64 Pn, E, Gc, F, GS, V;                            \
        PACK2(Pn, pel, tel);                                \
        FMA2(E, Pn, M1, Pc);      /* E = Pc - Pn */         \
        MUL2(Gc, E, E);                                     \
        ADD2(F, Ep, E);                                     \
        ADD2(GS, Gp, Gc);                                   \
        FMA2(V, F, F, GS);        /* {6vp, 6vt} >= 0 */     \
        if (v) {                                            \
            ADD2(accV, accV, V);                            \
            float _vp, _vt;                                 \
            UNPACK2(_vp, _vt, V);                           \
            accR += sqrt_approx(_vp * _vt);                 \
        }                                                   \
        Ep = E; Gp = Gc; Pc = Pn;                           \
    } while (0)

__global__ void __launch_bounds__(NTHREADS)
vol_loss_tma(const float* __restrict__ pred, const float* __restrict__ targ,
             float* __restrict__ out) {
    __shared__ alignas(16) float sp[CHUNK + EXTRA];
    __shared__ alignas(16) float sq[CHUNK + EXTRA];
    __shared__ alignas(8)  u64   mbar_store;
    __shared__ float red[NTHREADS / 32];
    __shared__ bool  is_last;

    const int t = threadIdx.x;
    const int row  = blockIdx.x >> 1;
    const int half = blockIdx.x & 1;
    const float* pg = pred + (((size_t)row << 13) + ((size_t)half << 12));
    const float* tg = targ + (((size_t)row << 13) + ((size_t)half << 12));
    const bool lastblk = (blockIdx.x == NBLOCKS - 1);
    const uint32_t mbar = smem_u32(&mbar_store);

    // Last block: peek region is not bulk-loaded (would read past the array);
    // zero it — windows using it are predicated off anyway.
    if (lastblk && t < EXTRA) { sp[CHUNK + t] = 0.0f; sq[CHUNK + t] = 0.0f; }
    if (t == 0) {
        asm volatile("mbarrier.init.shared::cta.b64 [%0], 1;" :: "r"(mbar) : "memory");
    }
    __syncthreads();   // init + zero-stores visible to all

    if (t == 0) {
        const uint32_t bytes = (lastblk ? CHUNK : CHUNK + EXTRA) * 4u;
        asm volatile("mbarrier.arrive.expect_tx.shared::cta.b64 _, [%0], %1;"
                     :: "r"(mbar), "r"(bytes * 2u) : "memory");
        uint32_t dp = smem_u32(sp), dq = smem_u32(sq);
        asm volatile(
            "cp.async.bulk.shared::cluster.global.mbarrier::complete_tx::bytes "
            "[%0], [%1], %2, [%3];"
            :: "r"(dp), "l"(pg), "r"(bytes), "r"(mbar) : "memory");
        asm volatile(
            "cp.async.bulk.shared::cluster.global.mbarrier::complete_tx::bytes "
            "[%0], [%1], %2, [%3];"
            :: "r"(dq), "l"(tg), "r"(bytes), "r"(mbar) : "memory");
    }
    mbar_wait(mbar, 0);

    // Compute: 4 passes, 4 windows/thread/pass. float4 LDS at 16B stride is
    // bank-conflict-free; float2 peeks are cheap.
    const int gwbase = half << 12;   // global window offset of this chunk
    u64 M1, accV;
    PACK2(M1,   -1.0f, -1.0f);
    PACK2(accV,  0.0f,  0.0f);
    float accR = 0.0f;

    #pragma unroll
    for (int p = 0; p < 4; ++p) {
        const int idx = p * (NTHREADS * 4) + (t << 2);
        float4 P = *(const float4*)&sp[idx];
        float4 T = *(const float4*)&sq[idx];
        float2 Pp = *(const float2*)&sp[idx + 4];
        float2 Tp = *(const float2*)&sq[idx + 4];
        const int gw = gwbase + idx;

        u64 P0, Pc, Ep, Gp;
        PACK2(P0, P.x, T.x);
        PACK2(Pc, P.y, T.y);
        FMA2(Ep, Pc, M1, P0);
        MUL2(Gp, Ep, Ep);
        STEP(P.z,  T.z,  (gw + 0) < L_OUT);
        STEP(P.w,  T.w,  (gw + 1) < L_OUT);
        STEP(Pp.x, Tp.x, (gw + 2) < L_OUT);
        STEP(Pp.y, Tp.y, (gw + 3) < L_OUT);
    }

    float vps, vts;
    UNPACK2(vps, vts, accV);
    float acc = (vps + vts) - 2.0f * accR;   // still scaled by 6

    // Deterministic intra-block reduction.
    const int lane = t & 31;
    #pragma unroll
    for (int o = 16; o > 0; o >>= 1)
        acc += __shfl_down_sync(0xffffffffu, acc, o);
    if (lane == 0) red[t >> 5] = acc;
    __syncthreads();

    if (t == 0) {
        float v = 0.0f;
        #pragma unroll
        for (int w = 0; w < NTHREADS / 32; ++w) v += red[w];
        g_partials[blockIdx.x] = v;
        __threadfence();
        unsigned int old = atomicAdd(&g_counter, 1u);
        is_last = ((old + 1u) % (unsigned)NBLOCKS) == 0u;
    }
    __syncthreads();

    if (!is_last) return;

    // Last-arriving block: deterministic final reduction; fold deferred /6.
    __shared__ double sh[NTHREADS];
    double s = 0.0;
    for (int i = t; i < NBLOCKS; i += NTHREADS)
        s += (double)g_partials[i];
    sh[t] = s;
    __syncthreads();
    #pragma unroll
    for (int stride = NTHREADS / 2; stride > 0; stride >>= 1) {
        if (t < stride) sh[t] += sh[t + stride];
        __syncthreads();
    }
    if (t == 0)
        out[0] = (float)(sh[0] / (6.0 * (double)B_ROWS * (double)L_OUT));
}

extern "C" void kernel_launch(void* const* d_in, const int* in_sizes, int n_in,
                              void* d_out, int out_size) {
    const float* pred = (const float*)d_in[0];
    const float* targ = (const float*)d_in[1];
    vol_loss_tma<<<NBLOCKS, NTHREADS>>>(pred, targ, (float*)d_out);
}